// round 6
// baseline (speedup 1.0000x reference)
#include <cuda_runtime.h>
#include <cstdint>
#include <cstddef>

// ============================================================================
// Problem constants
// ============================================================================
#define N_TOK 4096
#define DIM   1024

// GEMM tile config: mma.sync m16n8k8 tf32 (legacy HMMA — no sm_103a features)
#define BM 128
#define BN 128
#define BK 32
#define LDR 36                                   // 32 + 4 pad floats per smem row
#define TILE_FLOATS (128 * LDR)                  // 4608 floats = 18432 B
#define BUF_FLOATS  (2 * TILE_FLOATS)            // A + B = 9216 floats
#define SMEM_ALLOC  (2 * BUF_FLOATS * 4)         // 73728 B (double buffered)

// ============================================================================
// Device scratch (__device__ globals per allocation-free rule)
// ============================================================================
static __device__ __align__(256) float g_text_r [N_TOK * DIM];
static __device__ __align__(256) float g_image_r[N_TOK * DIM];
static __device__ __align__(256) float g_wt_r   [DIM * DIM];
static __device__ __align__(256) float g_wi_r   [DIM * DIM];
static __device__ __align__(256) float g_imT    [DIM * N_TOK];   // image^T (tf32)
static __device__ __align__(256) float g_txT    [DIM * N_TOK];   // text^T  (tf32)
static __device__ __align__(256) float g_t      [N_TOK * DIM];   // text proj (tf32)
static __device__ __align__(256) float g_i      [N_TOK * DIM];   // image proj (tf32)
static __device__ __align__(256) float g_P      [(size_t)N_TOK * N_TOK]; // exp(L/32)
static __device__ __align__(256) float g_PT     [(size_t)N_TOK * N_TOK]; // P^T
static __device__ __align__(256) float g_rowsum [N_TOK];
static __device__ __align__(256) float g_colsum [N_TOK];

// ============================================================================
// Helpers
// ============================================================================
__device__ __forceinline__ float rna_tf32(float x) {
    uint32_t o, in = __float_as_uint(x);
    asm("cvt.rna.tf32.f32 %0, %1;" : "=r"(o) : "r"(in));
    return __uint_as_float(o);
}

__device__ __forceinline__ void cp_async16(void* dst_smem, const void* src) {
    uint32_t dst;
    asm("{ .reg .u64 t; cvta.to.shared.u64 t, %1; cvt.u32.u64 %0, t; }" : "=r"(dst) : "l"(dst_smem));
    asm volatile("cp.async.cg.shared.global [%0], [%1], 16;" :: "r"(dst), "l"(src) : "memory");
}
#define CP_COMMIT() asm volatile("cp.async.commit_group;" ::: "memory")
#define CP_WAIT(n)  asm volatile("cp.async.wait_group %0;" :: "n"(n) : "memory")

__device__ __forceinline__ void mma_tf32(float& d0, float& d1, float& d2, float& d3,
                                         uint32_t a0, uint32_t a1, uint32_t a2, uint32_t a3,
                                         uint32_t b0, uint32_t b1) {
    asm volatile(
        "mma.sync.aligned.m16n8k8.row.col.f32.tf32.tf32.f32 "
        "{%0,%1,%2,%3}, {%4,%5,%6,%7}, {%8,%9}, {%0,%1,%2,%3};"
        : "+f"(d0), "+f"(d1), "+f"(d2), "+f"(d3)
        : "r"(a0), "r"(a1), "r"(a2), "r"(a3), "r"(b0), "r"(b1));
}

// ============================================================================
// GEMM:  D[m,n] = sum_k A[m,k] * B[n,k]   (NT, both K-major, tf32 operands)
// MODE 0: C[m,n] = rna(D + bias[n])                        (projections)
// MODE 1: e = rna(exp(D/32)); C[m,n]=e; C2[n,m]=e          (logits -> P, P^T)
// MODE 2: C[m,n] = D * scale[0] / denom[m]                 (attn @ V)
// ============================================================================
template <int MODE>
__global__ __launch_bounds__(256, 2)
void gemm_mma(const float* __restrict__ A, const float* __restrict__ B,
              int K, int ldA, int ldB,
              float* __restrict__ C, int ldC,
              float* __restrict__ C2, int ldC2,
              const float* __restrict__ bias,
              const float* __restrict__ denom,
              const float* __restrict__ scale)
{
    extern __shared__ float smemf[];
    const int tid = threadIdx.x;
    const int wid = tid >> 5;
    const int lid = tid & 31;
    const int g   = lid >> 2;     // group id (0..7)
    const int q   = lid & 3;      // thread-in-group (0..3)
    const int mw  = wid >> 2;     // warp m index (0..1) -> 64 rows
    const int nw  = wid & 3;      // warp n index (0..3) -> 32 cols
    const int m0  = blockIdx.y * BM;
    const int n0  = blockIdx.x * BN;

    const float* __restrict__ Ab = A + (size_t)m0 * ldA;
    const float* __restrict__ Bb = B + (size_t)n0 * ldB;

    float acc[4][4][4];
    #pragma unroll
    for (int i = 0; i < 4; i++)
        #pragma unroll
        for (int j = 0; j < 4; j++)
            #pragma unroll
            for (int c = 0; c < 4; c++) acc[i][j][c] = 0.0f;

    const int NK = K / BK;

    auto fill = [&](int kt, int bufI) {
        const int kofs = kt * BK;
        float* dstA = smemf + bufI * BUF_FLOATS;
        float* dstB = dstA + TILE_FLOATS;
        #pragma unroll
        for (int i = 0; i < 8; i++) {
            const int idx = tid + i * 256;      // 0..2047 16B-chunks
            const int isB = idx >> 10;
            const int cc  = idx & 1023;
            const int row = cc >> 3;
            const int ch  = cc & 7;
            const float* src = (isB ? (Bb + (size_t)row * ldB) : (Ab + (size_t)row * ldA))
                               + kofs + ch * 4;
            float* dst = (isB ? dstB : dstA) + row * LDR + ch * 4;
            cp_async16(dst, src);
        }
        CP_COMMIT();
    };

    fill(0, 0);
    if (NK > 1) fill(1, 1);

    for (int kt = 0; kt < NK; kt++) {
        const int b = kt & 1;
        if (kt + 1 < NK) { CP_WAIT(1); } else { CP_WAIT(0); }
        __syncthreads();

        const float* As = smemf + b * BUF_FLOATS;
        const float* Bs = As + TILE_FLOATS;
        const float* Aw = As + (mw * 64) * LDR;       // warp's A rows
        const float* Bw = Bs + (nw * 32) * LDR;       // warp's B rows

        #pragma unroll
        for (int ks = 0; ks < 4; ks++) {
            const int k0 = ks * 8;
            uint32_t af[4][4];
            #pragma unroll
            for (int i = 0; i < 4; i++) {
                const float* ap = Aw + (i * 16 + g) * LDR + k0 + q;
                af[i][0] = __float_as_uint(ap[0]);
                af[i][1] = __float_as_uint(ap[8 * LDR]);
                af[i][2] = __float_as_uint(ap[4]);
                af[i][3] = __float_as_uint(ap[8 * LDR + 4]);
            }
            uint32_t bf[4][2];
            #pragma unroll
            for (int j = 0; j < 4; j++) {
                const float* bp = Bw + (j * 8 + g) * LDR + k0 + q;
                bf[j][0] = __float_as_uint(bp[0]);
                bf[j][1] = __float_as_uint(bp[4]);
            }
            #pragma unroll
            for (int i = 0; i < 4; i++)
                #pragma unroll
                for (int j = 0; j < 4; j++)
                    mma_tf32(acc[i][j][0], acc[i][j][1], acc[i][j][2], acc[i][j][3],
                             af[i][0], af[i][1], af[i][2], af[i][3],
                             bf[j][0], bf[j][1]);
        }
        __syncthreads();
        if (kt + 2 < NK) fill(kt + 2, b);
    }

    // ---------------- Epilogue ----------------
    // Thread's values: rows m0+mw*64+i*16+{g, g+8}, cols n0+nw*32+j*8+{2q, 2q+1}
    const float scale0 = (MODE == 2) ? scale[0] : 0.0f;

    #pragma unroll
    for (int i = 0; i < 4; i++) {
        const int r0 = mw * 64 + i * 16 + g;
        const int r1 = r0 + 8;
        float sc0 = 1.0f, sc1 = 1.0f;
        if (MODE == 2) {
            sc0 = scale0 / __ldg(&denom[m0 + r0]);
            sc1 = scale0 / __ldg(&denom[m0 + r1]);
        }
        #pragma unroll
        for (int j = 0; j < 4; j++) {
            const int c0 = nw * 32 + j * 8 + 2 * q;
            float v00 = acc[i][j][0], v01 = acc[i][j][1];
            float v10 = acc[i][j][2], v11 = acc[i][j][3];
            if (MODE == 0) {
                const float b0 = __ldg(&bias[n0 + c0]);
                const float b1 = __ldg(&bias[n0 + c0 + 1]);
                v00 = rna_tf32(v00 + b0); v01 = rna_tf32(v01 + b1);
                v10 = rna_tf32(v10 + b0); v11 = rna_tf32(v11 + b1);
            } else if (MODE == 1) {
                v00 = rna_tf32(__expf(v00 * 0.03125f));
                v01 = rna_tf32(__expf(v01 * 0.03125f));
                v10 = rna_tf32(__expf(v10 * 0.03125f));
                v11 = rna_tf32(__expf(v11 * 0.03125f));
            } else {
                v00 *= sc0; v01 *= sc0;
                v10 *= sc1; v11 *= sc1;
            }
            // direct stores: 4 lanes cover 8 consecutive cols = one 32B sector
            C[(size_t)(m0 + r0) * ldC + n0 + c0]     = v00;
            C[(size_t)(m0 + r0) * ldC + n0 + c0 + 1] = v01;
            C[(size_t)(m0 + r1) * ldC + n0 + c0]     = v10;
            C[(size_t)(m0 + r1) * ldC + n0 + c0 + 1] = v11;
            if (MODE == 1) {
                // stage transposed into smem: bufT[n][m], stride 130
                float* bufT = smemf;
                bufT[(c0    ) * 130 + r0] = v00;
                bufT[(c0 + 1) * 130 + r0] = v01;
                bufT[(c0    ) * 130 + r1] = v10;
                bufT[(c0 + 1) * 130 + r1] = v11;
            }
            acc[i][j][0] = v00; acc[i][j][1] = v01;    // keep (unused further)
            acc[i][j][2] = v10; acc[i][j][3] = v11;
        }
    }

    if (MODE == 1) {
        __syncthreads();
        const float* bufT = smemf;
        // coalesced P^T stores: warp w handles n-rows [w*16, w*16+16)
        for (int r = wid * 16; r < wid * 16 + 16; r++) {
            float* dst = C2 + (size_t)(n0 + r) * ldC2 + m0;
            const float* src = bufT + r * 130;
            #pragma unroll
            for (int m = lid; m < 128; m += 32) dst[m] = src[m];
        }
    }
}

// ============================================================================
// Helper kernels
// ============================================================================
__global__ void round_k(const float4* __restrict__ in, float4* __restrict__ out, int n4) {
    int i = blockIdx.x * blockDim.x + threadIdx.x;
    if (i < n4) {
        float4 a = in[i];
        a.x = rna_tf32(a.x); a.y = rna_tf32(a.y); a.z = rna_tf32(a.z); a.w = rna_tf32(a.w);
        out[i] = a;
    }
}

// out[x][y] = rna(in[y][x]);  in: [rows x cols], out: [cols x rows]
__global__ void transpose_round_k(const float* __restrict__ in, float* __restrict__ out,
                                  int rows, int cols) {
    __shared__ float t[32][33];
    const int x0 = blockIdx.x * 32, y0 = blockIdx.y * 32;
    for (int j = threadIdx.y; j < 32; j += 8)
        t[j][threadIdx.x] = rna_tf32(in[(size_t)(y0 + j) * cols + x0 + threadIdx.x]);
    __syncthreads();
    for (int j = threadIdx.y; j < 32; j += 8)
        out[(size_t)(x0 + j) * rows + y0 + threadIdx.x] = t[threadIdx.x][j];
}

__global__ void rowsum_k(const float* __restrict__ P, float* __restrict__ out, int ncols) {
    __shared__ float red[256];
    const float4* row = (const float4*)(P + (size_t)blockIdx.x * ncols);
    float s = 0.0f;
    for (int j = threadIdx.x; j < (ncols >> 2); j += 256) {
        float4 a = row[j];
        s += (a.x + a.y) + (a.z + a.w);
    }
    red[threadIdx.x] = s;
    __syncthreads();
    for (int o = 128; o > 0; o >>= 1) {
        if (threadIdx.x < o) red[threadIdx.x] += red[threadIdx.x + o];
        __syncthreads();
    }
    if (threadIdx.x == 0) out[blockIdx.x] = red[0];
}

// ============================================================================
// Host launch
// ============================================================================
extern "C" void kernel_launch(void* const* d_in, const int* in_sizes, int n_in,
                              void* d_out, int out_size) {
    const float* text    = (const float*)d_in[0];
    const float* image   = (const float*)d_in[1];
    const float* w_text  = (const float*)d_in[2];
    const float* b_text  = (const float*)d_in[3];
    const float* w_image = (const float*)d_in[4];
    const float* b_image = (const float*)d_in[5];
    const float* s_TI    = (const float*)d_in[6];
    const float* s_IT    = (const float*)d_in[7];
    float* out = (float*)d_out;

    float *text_r, *image_r, *wt_r, *wi_r, *imT, *txT, *tproj, *iproj, *P, *PT, *rs, *cs;
    cudaGetSymbolAddress((void**)&text_r,  g_text_r);
    cudaGetSymbolAddress((void**)&image_r, g_image_r);
    cudaGetSymbolAddress((void**)&wt_r,    g_wt_r);
    cudaGetSymbolAddress((void**)&wi_r,    g_wi_r);
    cudaGetSymbolAddress((void**)&imT,     g_imT);
    cudaGetSymbolAddress((void**)&txT,     g_txT);
    cudaGetSymbolAddress((void**)&tproj,   g_t);
    cudaGetSymbolAddress((void**)&iproj,   g_i);
    cudaGetSymbolAddress((void**)&P,       g_P);
    cudaGetSymbolAddress((void**)&PT,      g_PT);
    cudaGetSymbolAddress((void**)&rs,      g_rowsum);
    cudaGetSymbolAddress((void**)&cs,      g_colsum);

    cudaFuncSetAttribute((const void*)gemm_mma<0>, cudaFuncAttributeMaxDynamicSharedMemorySize, SMEM_ALLOC);
    cudaFuncSetAttribute((const void*)gemm_mma<1>, cudaFuncAttributeMaxDynamicSharedMemorySize, SMEM_ALLOC);
    cudaFuncSetAttribute((const void*)gemm_mma<2>, cudaFuncAttributeMaxDynamicSharedMemorySize, SMEM_ALLOC);

    // 1) tf32-round inputs / weights
    {
        int n4 = N_TOK * DIM / 4;
        round_k<<<(n4 + 255) / 256, 256>>>((const float4*)text,  (float4*)text_r,  n4);
        round_k<<<(n4 + 255) / 256, 256>>>((const float4*)image, (float4*)image_r, n4);
        int w4 = DIM * DIM / 4;
        round_k<<<(w4 + 255) / 256, 256>>>((const float4*)w_text,  (float4*)wt_r, w4);
        round_k<<<(w4 + 255) / 256, 256>>>((const float4*)w_image, (float4*)wi_r, w4);
    }
    // 2) transposes (rounded) for G4/G5 B operands
    {
        dim3 blk(32, 8);
        dim3 grd(DIM / 32, N_TOK / 32);
        transpose_round_k<<<grd, blk>>>(image, imT, N_TOK, DIM);
        transpose_round_k<<<grd, blk>>>(text,  txT, N_TOK, DIM);
    }
    // 3) projections:  t = text @ w_text^T + b_text   (NT: B = W[out,in] K-major)
    {
        dim3 grd(DIM / BN, N_TOK / BM);
        gemm_mma<0><<<grd, 256, SMEM_ALLOC>>>(text_r,  wt_r, DIM, DIM, DIM,
                                              tproj, DIM, nullptr, 0, b_text, nullptr, nullptr);
        gemm_mma<0><<<grd, 256, SMEM_ALLOC>>>(image_r, wi_r, DIM, DIM, DIM,
                                              iproj, DIM, nullptr, 0, b_image, nullptr, nullptr);
    }
    // 4) logits + exp:  P = exp((t @ i^T)/32),  PT = P^T
    {
        dim3 grd(N_TOK / BN, N_TOK / BM);
        gemm_mma<1><<<grd, 256, SMEM_ALLOC>>>(tproj, iproj, DIM, DIM, DIM,
                                              P, N_TOK, PT, N_TOK, nullptr, nullptr, nullptr);
    }
    // 5) softmax denominators
    rowsum_k<<<N_TOK, 256>>>(P,  rs, N_TOK);
    rowsum_k<<<N_TOK, 256>>>(PT, cs, N_TOK);
    // 6) outputs: out1 = (P @ image)*s_TI/rowsum ; out2 = (PT @ text)*s_IT/colsum
    {
        dim3 grd(DIM / BN, N_TOK / BM);
        gemm_mma<2><<<grd, 256, SMEM_ALLOC>>>(P,  imT, N_TOK, N_TOK, N_TOK,
                                              out, DIM, nullptr, 0, nullptr, rs, s_TI);
        gemm_mma<2><<<grd, 256, SMEM_ALLOC>>>(PT, txT, N_TOK, N_TOK, N_TOK,
                                              out + (size_t)N_TOK * DIM, DIM, nullptr, 0,
                                              nullptr, cs, s_IT);
    }
}

// round 8
// speedup vs baseline: 2.0640x; 2.0640x over previous
#include <cuda_runtime.h>
#include <cuda_fp16.h>
#include <cstdint>
#include <cstddef>

// ============================================================================
// Problem constants
// ============================================================================
#define N_TOK 4096
#define DIM   1024

// ---- fp16 mma.sync m16n8k16 GEMM config ----
#define BM 128
#define BN 128
#define BKH 64                        // fp16 elems per K-stage (128 B/row)
#define LDH 72                        // padded smem row stride in halves (144 B)
#define TILE_H (128 * LDH)            // halves per tile (A or B)
#define BUF_H  (2 * TILE_H)           // A + B halves per stage
#define SMEM_H (2 * BUF_H * 2)        // bytes, double buffered = 73728

// ============================================================================
// Device scratch (fp16 planes; __device__ globals per allocation-free rule)
// ============================================================================
static __device__ __align__(256) __half g_tx  [N_TOK * DIM];
static __device__ __align__(256) __half g_im  [N_TOK * DIM];
static __device__ __align__(256) __half g_wt  [DIM * DIM];
static __device__ __align__(256) __half g_wi  [DIM * DIM];
static __device__ __align__(256) __half g_imT [DIM * N_TOK];
static __device__ __align__(256) __half g_txT [DIM * N_TOK];
static __device__ __align__(256) __half g_t   [N_TOK * DIM];
static __device__ __align__(256) __half g_i   [N_TOK * DIM];
static __device__ __align__(256) __half g_P   [(size_t)N_TOK * N_TOK];
static __device__ __align__(256) __half g_PT  [(size_t)N_TOK * N_TOK];
static __device__ __align__(256) float  g_rowsum[N_TOK];
static __device__ __align__(256) float  g_colsum[N_TOK];

// ============================================================================
// Helpers
// ============================================================================
__device__ __forceinline__ void cp_async16(void* dst_smem, const void* src) {
    uint32_t dst;
    asm("{ .reg .u64 t; cvta.to.shared.u64 t, %1; cvt.u32.u64 %0, t; }" : "=r"(dst) : "l"(dst_smem));
    asm volatile("cp.async.cg.shared.global [%0], [%1], 16;" :: "r"(dst), "l"(src) : "memory");
}
#define CP_COMMIT() asm volatile("cp.async.commit_group;" ::: "memory")
#define CP_WAIT(n)  asm volatile("cp.async.wait_group %0;" :: "n"(n) : "memory")

__device__ __forceinline__ uint32_t smem_addr32(const void* p) {
    uint32_t a;
    asm("{ .reg .u64 t; cvta.to.shared.u64 t, %1; cvt.u32.u64 %0, t; }" : "=r"(a) : "l"(p));
    return a;
}

__device__ __forceinline__ void ldsm_x4(uint32_t& r0, uint32_t& r1, uint32_t& r2, uint32_t& r3,
                                        uint32_t addr) {
    asm volatile("ldmatrix.sync.aligned.m8n8.x4.shared.b16 {%0,%1,%2,%3}, [%4];"
                 : "=r"(r0), "=r"(r1), "=r"(r2), "=r"(r3) : "r"(addr));
}

__device__ __forceinline__ void mma_f16(float& d0, float& d1, float& d2, float& d3,
                                        uint32_t a0, uint32_t a1, uint32_t a2, uint32_t a3,
                                        uint32_t b0, uint32_t b1) {
    asm volatile(
        "mma.sync.aligned.m16n8k16.row.col.f32.f16.f16.f32 "
        "{%0,%1,%2,%3}, {%4,%5,%6,%7}, {%8,%9}, {%0,%1,%2,%3};"
        : "+f"(d0), "+f"(d1), "+f"(d2), "+f"(d3)
        : "r"(a0), "r"(a1), "r"(a2), "r"(a3), "r"(b0), "r"(b1));
}

// ============================================================================
// fp16 GEMM:  D[m,n] = sum_k A[m,k] * B[n,k]   (NT, both K-major, fp32 accum)
// MODE 0: C[m,n] = h(D + bias[n])                           (projections, fp16 out)
// MODE 1: e = h(exp(D/32)); C[m,n]=e; C2[n,m]=e             (logits -> P, P^T, fp16)
// MODE 2: Cf[m,n] = D * scale[0] / denom[m]                 (attn @ V, fp32 out)
// ============================================================================
template <int MODE>
__global__ __launch_bounds__(256, 2)
void gemm_h(const __half* __restrict__ A, const __half* __restrict__ B,
            int K, int ldA, int ldB,
            __half* __restrict__ C, int ldC,
            __half* __restrict__ C2, int ldC2,
            float* __restrict__ Cf,
            const float* __restrict__ bias,
            const float* __restrict__ denom,
            const float* __restrict__ scale)
{
    extern __shared__ __half smemh[];
    const int tid = threadIdx.x;
    const int wid = tid >> 5;
    const int lid = tid & 31;
    const int mw  = wid >> 2;       // 0..1 -> 64 rows
    const int nw  = wid & 3;        // 0..3 -> 32 cols
    const int m0  = blockIdx.y * BM;
    const int n0  = blockIdx.x * BN;

    const __half* __restrict__ Ab = A + (size_t)m0 * ldA;
    const __half* __restrict__ Bb = B + (size_t)n0 * ldB;

    const uint32_t sbase = smem_addr32(smemh);

    float acc[4][4][4];
    #pragma unroll
    for (int i = 0; i < 4; i++)
        #pragma unroll
        for (int j = 0; j < 4; j++)
            #pragma unroll
            for (int c = 0; c < 4; c++) acc[i][j][c] = 0.0f;

    const int NK = K / BKH;

    auto fill = [&](int kt, int bufI) {
        const int kofs = kt * BKH;
        char* base = (char*)smemh + bufI * BUF_H * 2;
        #pragma unroll
        for (int i = 0; i < 8; i++) {
            const int idx = tid + i * 256;        // 0..2047 16B-chunks
            const int isB = idx >> 10;
            const int cc  = idx & 1023;
            const int row = cc >> 3;              // 0..127
            const int ch  = cc & 7;               // 16B chunk (8 halves)
            const __half* src = (isB ? (Bb + (size_t)row * ldB) : (Ab + (size_t)row * ldA))
                                + kofs + ch * 8;
            char* dst = base + (isB ? TILE_H * 2 : 0) + row * (LDH * 2) + ch * 16;
            cp_async16(dst, src);
        }
        CP_COMMIT();
    };

    fill(0, 0);
    if (NK > 1) fill(1, 1);

    // per-lane ldmatrix address offsets (bytes)
    const uint32_t a_lane = (uint32_t)(((lid & 15) * LDH + (lid >> 4) * 8) * 2);
    const uint32_t b_lane = (uint32_t)((((lid & 7) + ((lid >> 4) << 3)) * LDH
                                        + ((lid >> 3) & 1) * 8) * 2);

    for (int kt = 0; kt < NK; kt++) {
        const int b = kt & 1;
        if (kt + 1 < NK) { CP_WAIT(1); } else { CP_WAIT(0); }
        __syncthreads();

        const uint32_t Abase = sbase + (uint32_t)(b * BUF_H * 2) + (uint32_t)(mw * 64 * LDH * 2);
        const uint32_t Bbase = sbase + (uint32_t)(b * BUF_H * 2) + (uint32_t)(TILE_H * 2)
                             + (uint32_t)(nw * 32 * LDH * 2);

        #pragma unroll
        for (int ks = 0; ks < 4; ks++) {
            const uint32_t kb = (uint32_t)(ks * 16 * 2);
            uint32_t af[4][4];
            #pragma unroll
            for (int i = 0; i < 4; i++)
                ldsm_x4(af[i][0], af[i][1], af[i][2], af[i][3],
                        Abase + (uint32_t)(i * 16 * LDH * 2) + kb + a_lane);
            uint32_t bf[4][2];
            #pragma unroll
            for (int jj = 0; jj < 2; jj++)
                ldsm_x4(bf[jj * 2][0], bf[jj * 2][1], bf[jj * 2 + 1][0], bf[jj * 2 + 1][1],
                        Bbase + (uint32_t)(jj * 16 * LDH * 2) + kb + b_lane);
            #pragma unroll
            for (int i = 0; i < 4; i++)
                #pragma unroll
                for (int j = 0; j < 4; j++)
                    mma_f16(acc[i][j][0], acc[i][j][1], acc[i][j][2], acc[i][j][3],
                            af[i][0], af[i][1], af[i][2], af[i][3],
                            bf[j][0], bf[j][1]);
        }
        __syncthreads();
        if (kt + 2 < NK) fill(kt + 2, b);
    }

    // ---------------- Epilogue ----------------
    // Thread values: rows m0+mw*64+i*16+{g, g+8}, cols n0+nw*32+j*8+{2q, 2q+1}
    const int g = lid >> 2;
    const int q = lid & 3;
    const float scale0 = (MODE == 2) ? scale[0] : 0.0f;
    __half* bufT = smemh;     // MODE 1 transpose staging: [128 n][132 m] halves

    #pragma unroll
    for (int i = 0; i < 4; i++) {
        const int r0 = mw * 64 + i * 16 + g;
        const int r1 = r0 + 8;
        float sc0 = 1.0f, sc1 = 1.0f;
        if (MODE == 2) {
            sc0 = scale0 / __ldg(&denom[m0 + r0]);
            sc1 = scale0 / __ldg(&denom[m0 + r1]);
        }
        #pragma unroll
        for (int j = 0; j < 4; j++) {
            const int c0 = nw * 32 + j * 8 + 2 * q;
            float v00 = acc[i][j][0], v01 = acc[i][j][1];
            float v10 = acc[i][j][2], v11 = acc[i][j][3];
            if (MODE == 0) {
                const float b0 = __ldg(&bias[n0 + c0]);
                const float b1 = __ldg(&bias[n0 + c0 + 1]);
                __half2 h0 = __floats2half2_rn(v00 + b0, v01 + b1);
                __half2 h1 = __floats2half2_rn(v10 + b0, v11 + b1);
                *(__half2*)(C + (size_t)(m0 + r0) * ldC + n0 + c0) = h0;
                *(__half2*)(C + (size_t)(m0 + r1) * ldC + n0 + c0) = h1;
            } else if (MODE == 1) {
                __half2 h0 = __floats2half2_rn(__expf(v00 * 0.03125f), __expf(v01 * 0.03125f));
                __half2 h1 = __floats2half2_rn(__expf(v10 * 0.03125f), __expf(v11 * 0.03125f));
                *(__half2*)(C + (size_t)(m0 + r0) * ldC + n0 + c0) = h0;
                *(__half2*)(C + (size_t)(m0 + r1) * ldC + n0 + c0) = h1;
                bufT[(c0    ) * 132 + r0] = __low2half(h0);
                bufT[(c0 + 1) * 132 + r0] = __high2half(h0);
                bufT[(c0    ) * 132 + r1] = __low2half(h1);
                bufT[(c0 + 1) * 132 + r1] = __high2half(h1);
            } else {
                float2 f0 = make_float2(v00 * sc0, v01 * sc0);
                float2 f1 = make_float2(v10 * sc1, v11 * sc1);
                *(float2*)(Cf + (size_t)(m0 + r0) * ldC + n0 + c0) = f0;
                *(float2*)(Cf + (size_t)(m0 + r1) * ldC + n0 + c0) = f1;
            }
        }
    }

    if (MODE == 1) {
        __syncthreads();
        // coalesced P^T stores: warp w handles n-rows [w*16, w*16+16)
        for (int r = wid * 16; r < wid * 16 + 16; r++) {
            uint32_t* dst32 = (uint32_t*)(C2 + (size_t)(n0 + r) * ldC2 + m0);
            const uint32_t* src32 = (const uint32_t*)(bufT + r * 132);
            dst32[lid]      = src32[lid];
            dst32[lid + 32] = src32[lid + 32];
        }
    }
}

// ============================================================================
// Helper kernels
// ============================================================================
__global__ void tohalf_k(const float4* __restrict__ in, __half2* __restrict__ out, int n4) {
    int i = blockIdx.x * blockDim.x + threadIdx.x;
    if (i < n4) {
        float4 a = in[i];
        out[2 * i]     = __floats2half2_rn(a.x, a.y);
        out[2 * i + 1] = __floats2half2_rn(a.z, a.w);
    }
}

// out[x][y] = h(in[y][x]);  in: fp32 [rows][cols], out: fp16 [cols][rows]
__global__ void transpose_h_k(const float* __restrict__ in, __half* __restrict__ out,
                              int rows, int cols) {
    __shared__ float t[32][33];
    const int x0 = blockIdx.x * 32, y0 = blockIdx.y * 32;
    for (int j = threadIdx.y; j < 32; j += 8)
        t[j][threadIdx.x] = in[(size_t)(y0 + j) * cols + x0 + threadIdx.x];
    __syncthreads();
    for (int j = threadIdx.y; j < 32; j += 8)
        out[(size_t)(x0 + j) * rows + y0 + threadIdx.x] = __float2half_rn(t[threadIdx.x][j]);
}

__global__ void rowsum_h_k(const __half2* __restrict__ P2, float* __restrict__ out, int ncols) {
    __shared__ float red[256];
    const __half2* row = P2 + (size_t)blockIdx.x * (ncols / 2);
    float s = 0.0f;
    for (int j = threadIdx.x; j < ncols / 2; j += 256) {
        float2 v = __half22float2(row[j]);
        s += v.x + v.y;
    }
    red[threadIdx.x] = s;
    __syncthreads();
    for (int o = 128; o > 0; o >>= 1) {
        if (threadIdx.x < o) red[threadIdx.x] += red[threadIdx.x + o];
        __syncthreads();
    }
    if (threadIdx.x == 0) out[blockIdx.x] = red[0];
}

// ============================================================================
// Host launch
// ============================================================================
extern "C" void kernel_launch(void* const* d_in, const int* in_sizes, int n_in,
                              void* d_out, int out_size) {
    const float* text    = (const float*)d_in[0];
    const float* image   = (const float*)d_in[1];
    const float* w_text  = (const float*)d_in[2];
    const float* b_text  = (const float*)d_in[3];
    const float* w_image = (const float*)d_in[4];
    const float* b_image = (const float*)d_in[5];
    const float* s_TI    = (const float*)d_in[6];
    const float* s_IT    = (const float*)d_in[7];
    float* out = (float*)d_out;

    __half *tx, *im, *wt, *wi, *imT, *txT, *th, *ih, *P, *PT;
    float *rs, *cs;
    cudaGetSymbolAddress((void**)&tx,  g_tx);
    cudaGetSymbolAddress((void**)&im,  g_im);
    cudaGetSymbolAddress((void**)&wt,  g_wt);
    cudaGetSymbolAddress((void**)&wi,  g_wi);
    cudaGetSymbolAddress((void**)&imT, g_imT);
    cudaGetSymbolAddress((void**)&txT, g_txT);
    cudaGetSymbolAddress((void**)&th,  g_t);
    cudaGetSymbolAddress((void**)&ih,  g_i);
    cudaGetSymbolAddress((void**)&P,   g_P);
    cudaGetSymbolAddress((void**)&PT,  g_PT);
    cudaGetSymbolAddress((void**)&rs,  g_rowsum);
    cudaGetSymbolAddress((void**)&cs,  g_colsum);

    cudaFuncSetAttribute((const void*)gemm_h<0>, cudaFuncAttributeMaxDynamicSharedMemorySize, SMEM_H);
    cudaFuncSetAttribute((const void*)gemm_h<1>, cudaFuncAttributeMaxDynamicSharedMemorySize, SMEM_H);
    cudaFuncSetAttribute((const void*)gemm_h<2>, cudaFuncAttributeMaxDynamicSharedMemorySize, SMEM_H);

    // 1) fp16 conversions
    {
        int n4 = N_TOK * DIM / 4;
        tohalf_k<<<(n4 + 255) / 256, 256>>>((const float4*)text,  (__half2*)tx, n4);
        tohalf_k<<<(n4 + 255) / 256, 256>>>((const float4*)image, (__half2*)im, n4);
        int w4 = DIM * DIM / 4;
        tohalf_k<<<(w4 + 255) / 256, 256>>>((const float4*)w_text,  (__half2*)wt, w4);
        tohalf_k<<<(w4 + 255) / 256, 256>>>((const float4*)w_image, (__half2*)wi, w4);
    }
    // 2) fp16 transposes for G4/G5 B operands
    {
        dim3 blk(32, 8);
        dim3 grd(DIM / 32, N_TOK / 32);
        transpose_h_k<<<grd, blk>>>(image, imT, N_TOK, DIM);
        transpose_h_k<<<grd, blk>>>(text,  txT, N_TOK, DIM);
    }
    // 3) projections:  t = text @ w_text^T + b_text   (NT: B = W[out,in] K-major)
    {
        dim3 grd(DIM / BN, N_TOK / BM);
        gemm_h<0><<<grd, 256, SMEM_H>>>(tx, wt, DIM, DIM, DIM,
                                        th, DIM, nullptr, 0, nullptr, b_text, nullptr, nullptr);
        gemm_h<0><<<grd, 256, SMEM_H>>>(im, wi, DIM, DIM, DIM,
                                        ih, DIM, nullptr, 0, nullptr, b_image, nullptr, nullptr);
    }
    // 4) logits + exp:  P = exp((t @ i^T)/32),  PT = P^T
    {
        dim3 grd(N_TOK / BN, N_TOK / BM);
        gemm_h<1><<<grd, 256, SMEM_H>>>(th, ih, DIM, DIM, DIM,
                                        P, N_TOK, PT, N_TOK, nullptr, nullptr, nullptr, nullptr);
    }
    // 5) softmax denominators
    rowsum_h_k<<<N_TOK, 256>>>((const __half2*)P,  rs, N_TOK);
    rowsum_h_k<<<N_TOK, 256>>>((const __half2*)PT, cs, N_TOK);
    // 6) outputs: out1 = (P @ image)*s_TI/rowsum ; out2 = (PT @ text)*s_IT/colsum
    {
        dim3 grd(DIM / BN, N_TOK / BM);
        gemm_h<2><<<grd, 256, SMEM_H>>>(P,  imT, N_TOK, N_TOK, N_TOK,
                                        nullptr, DIM, nullptr, 0, out, nullptr, rs, s_TI);
        gemm_h<2><<<grd, 256, SMEM_H>>>(PT, txT, N_TOK, N_TOK, N_TOK,
                                        nullptr, DIM, nullptr, 0, out + (size_t)N_TOK * DIM,
                                        nullptr, cs, s_IT);
    }
}

// round 9
// speedup vs baseline: 2.1417x; 1.0376x over previous
#include <cuda_runtime.h>
#include <cuda_fp16.h>
#include <cstdint>
#include <cstddef>

// ============================================================================
// Problem constants
// ============================================================================
#define N_TOK 4096
#define DIM   1024

// ---- fp16 mma.sync m16n8k16 GEMM config ----
#define BM 128
#define BN 128
#define BKH 64                        // fp16 elems per K-stage (128 B/row)
#define LDH 72                        // padded smem row stride in halves (144 B)
#define TILE_H (128 * LDH)            // halves per tile (A or B)
#define BUF_H  (2 * TILE_H)           // A + B halves per stage
#define SMEM_H (2 * BUF_H * 2)        // bytes, double buffered = 73728

// ============================================================================
// Device scratch (fp16 planes; __device__ globals per allocation-free rule)
// ============================================================================
static __device__ __align__(256) __half g_tx  [N_TOK * DIM];
static __device__ __align__(256) __half g_im  [N_TOK * DIM];
static __device__ __align__(256) __half g_wt  [DIM * DIM];
static __device__ __align__(256) __half g_wi  [DIM * DIM];
static __device__ __align__(256) __half g_imT [DIM * N_TOK];
static __device__ __align__(256) __half g_txT [DIM * N_TOK];
static __device__ __align__(256) __half g_t   [N_TOK * DIM];
static __device__ __align__(256) __half g_i   [N_TOK * DIM];
static __device__ __align__(256) __half g_P   [(size_t)N_TOK * N_TOK];
static __device__ __align__(256) __half g_PT  [(size_t)N_TOK * N_TOK];
static __device__ __align__(256) float  g_rowsum[N_TOK];
static __device__ __align__(256) float  g_colsum[N_TOK];

// ============================================================================
// Helpers
// ============================================================================
__device__ __forceinline__ void cp_async16(void* dst_smem, const void* src) {
    uint32_t dst;
    asm("{ .reg .u64 t; cvta.to.shared.u64 t, %1; cvt.u32.u64 %0, t; }" : "=r"(dst) : "l"(dst_smem));
    asm volatile("cp.async.cg.shared.global [%0], [%1], 16;" :: "r"(dst), "l"(src) : "memory");
}
#define CP_COMMIT() asm volatile("cp.async.commit_group;" ::: "memory")
#define CP_WAIT(n)  asm volatile("cp.async.wait_group %0;" :: "n"(n) : "memory")

__device__ __forceinline__ uint32_t smem_addr32(const void* p) {
    uint32_t a;
    asm("{ .reg .u64 t; cvta.to.shared.u64 t, %1; cvt.u32.u64 %0, t; }" : "=r"(a) : "l"(p));
    return a;
}

__device__ __forceinline__ void ldsm_x4(uint32_t& r0, uint32_t& r1, uint32_t& r2, uint32_t& r3,
                                        uint32_t addr) {
    asm volatile("ldmatrix.sync.aligned.m8n8.x4.shared.b16 {%0,%1,%2,%3}, [%4];"
                 : "=r"(r0), "=r"(r1), "=r"(r2), "=r"(r3) : "r"(addr));
}

__device__ __forceinline__ void mma_f16(float& d0, float& d1, float& d2, float& d3,
                                        uint32_t a0, uint32_t a1, uint32_t a2, uint32_t a3,
                                        uint32_t b0, uint32_t b1) {
    asm volatile(
        "mma.sync.aligned.m16n8k16.row.col.f32.f16.f16.f32 "
        "{%0,%1,%2,%3}, {%4,%5,%6,%7}, {%8,%9}, {%0,%1,%2,%3};"
        : "+f"(d0), "+f"(d1), "+f"(d2), "+f"(d3)
        : "r"(a0), "r"(a1), "r"(a2), "r"(a3), "r"(b0), "r"(b1));
}

// ============================================================================
// fp16 GEMM:  D[m,n] = sum_k A[m,k] * B[n,k]   (NT, both K-major, fp32 accum)
// blockIdx.z in {0,1} selects pointer set (merged independent GEMMs).
// MODE 0: C[m,n] = h(D + bias[n])                           (projections, fp16 out)
// MODE 1: e = h(exp(D/32)); C[m,n]=e; C2[n,m]=e             (logits -> P, P^T, fp16)
// MODE 2: Cf[m,n] = D * scale[0] / denom[m]                 (attn @ V, fp32 out)
// ============================================================================
template <int MODE>
__global__ __launch_bounds__(256, 2)
void gemm_h(const __half* __restrict__ A0, const __half* __restrict__ B0,
            const __half* __restrict__ A1, const __half* __restrict__ B1,
            int K, int ldA, int ldB,
            __half* __restrict__ C0h, __half* __restrict__ C1h, int ldC,
            __half* __restrict__ C2, int ldC2,
            float* __restrict__ Cf0, float* __restrict__ Cf1,
            const float* __restrict__ bias0, const float* __restrict__ bias1,
            const float* __restrict__ denom0, const float* __restrict__ denom1,
            const float* __restrict__ scale0p, const float* __restrict__ scale1p)
{
    extern __shared__ __half smemh[];
    const int z   = blockIdx.z;
    const __half* __restrict__ A = z ? A1 : A0;
    const __half* __restrict__ B = z ? B1 : B0;
    __half* __restrict__ C       = z ? C1h : C0h;
    float*  __restrict__ Cf      = z ? Cf1 : Cf0;
    const float* __restrict__ bias  = z ? bias1  : bias0;
    const float* __restrict__ denom = z ? denom1 : denom0;
    const float* __restrict__ scale = z ? scale1p : scale0p;

    const int tid = threadIdx.x;
    const int wid = tid >> 5;
    const int lid = tid & 31;
    const int mw  = wid >> 2;       // 0..1 -> 64 rows
    const int nw  = wid & 3;        // 0..3 -> 32 cols
    const int m0  = blockIdx.y * BM;
    const int n0  = blockIdx.x * BN;

    const __half* __restrict__ Ab = A + (size_t)m0 * ldA;
    const __half* __restrict__ Bb = B + (size_t)n0 * ldB;

    const uint32_t sbase = smem_addr32(smemh);

    float acc[4][4][4];
    #pragma unroll
    for (int i = 0; i < 4; i++)
        #pragma unroll
        for (int j = 0; j < 4; j++)
            #pragma unroll
            for (int c = 0; c < 4; c++) acc[i][j][c] = 0.0f;

    const int NK = K / BKH;

    auto fill = [&](int kt, int bufI) {
        const int kofs = kt * BKH;
        char* base = (char*)smemh + bufI * BUF_H * 2;
        #pragma unroll
        for (int i = 0; i < 8; i++) {
            const int idx = tid + i * 256;        // 0..2047 16B-chunks
            const int isB = idx >> 10;
            const int cc  = idx & 1023;
            const int row = cc >> 3;              // 0..127
            const int ch  = cc & 7;               // 16B chunk (8 halves)
            const __half* src = (isB ? (Bb + (size_t)row * ldB) : (Ab + (size_t)row * ldA))
                                + kofs + ch * 8;
            char* dst = base + (isB ? TILE_H * 2 : 0) + row * (LDH * 2) + ch * 16;
            cp_async16(dst, src);
        }
        CP_COMMIT();
    };

    fill(0, 0);
    if (NK > 1) fill(1, 1);

    // per-lane ldmatrix address offsets (bytes)
    const uint32_t a_lane = (uint32_t)(((lid & 15) * LDH + (lid >> 4) * 8) * 2);
    const uint32_t b_lane = (uint32_t)((((lid & 7) + ((lid >> 4) << 3)) * LDH
                                        + ((lid >> 3) & 1) * 8) * 2);

    for (int kt = 0; kt < NK; kt++) {
        const int b = kt & 1;
        if (kt + 1 < NK) { CP_WAIT(1); } else { CP_WAIT(0); }
        __syncthreads();

        const uint32_t Abase = sbase + (uint32_t)(b * BUF_H * 2) + (uint32_t)(mw * 64 * LDH * 2);
        const uint32_t Bbase = sbase + (uint32_t)(b * BUF_H * 2) + (uint32_t)(TILE_H * 2)
                             + (uint32_t)(nw * 32 * LDH * 2);

        #pragma unroll
        for (int ks = 0; ks < 4; ks++) {
            const uint32_t kb = (uint32_t)(ks * 16 * 2);
            uint32_t af[4][4];
            #pragma unroll
            for (int i = 0; i < 4; i++)
                ldsm_x4(af[i][0], af[i][1], af[i][2], af[i][3],
                        Abase + (uint32_t)(i * 16 * LDH * 2) + kb + a_lane);
            uint32_t bf[4][2];
            #pragma unroll
            for (int jj = 0; jj < 2; jj++)
                ldsm_x4(bf[jj * 2][0], bf[jj * 2][1], bf[jj * 2 + 1][0], bf[jj * 2 + 1][1],
                        Bbase + (uint32_t)(jj * 16 * LDH * 2) + kb + b_lane);
            #pragma unroll
            for (int i = 0; i < 4; i++)
                #pragma unroll
                for (int j = 0; j < 4; j++)
                    mma_f16(acc[i][j][0], acc[i][j][1], acc[i][j][2], acc[i][j][3],
                            af[i][0], af[i][1], af[i][2], af[i][3],
                            bf[j][0], bf[j][1]);
        }
        __syncthreads();
        if (kt + 2 < NK) fill(kt + 2, b);
    }

    // ---------------- Epilogue ----------------
    const int g = lid >> 2;
    const int q = lid & 3;
    const float sc_glob = (MODE == 2) ? scale[0] : 0.0f;
    __half* bufT = smemh;     // MODE 1 transpose staging: [128 n][132 m] halves

    #pragma unroll
    for (int i = 0; i < 4; i++) {
        const int r0 = mw * 64 + i * 16 + g;
        const int r1 = r0 + 8;
        float sc0 = 1.0f, sc1 = 1.0f;
        if (MODE == 2) {
            sc0 = sc_glob / __ldg(&denom[m0 + r0]);
            sc1 = sc_glob / __ldg(&denom[m0 + r1]);
        }
        #pragma unroll
        for (int j = 0; j < 4; j++) {
            const int c0 = nw * 32 + j * 8 + 2 * q;
            float v00 = acc[i][j][0], v01 = acc[i][j][1];
            float v10 = acc[i][j][2], v11 = acc[i][j][3];
            if (MODE == 0) {
                const float b0 = __ldg(&bias[n0 + c0]);
                const float b1 = __ldg(&bias[n0 + c0 + 1]);
                __half2 h0 = __floats2half2_rn(v00 + b0, v01 + b1);
                __half2 h1 = __floats2half2_rn(v10 + b0, v11 + b1);
                *(__half2*)(C + (size_t)(m0 + r0) * ldC + n0 + c0) = h0;
                *(__half2*)(C + (size_t)(m0 + r1) * ldC + n0 + c0) = h1;
            } else if (MODE == 1) {
                __half2 h0 = __floats2half2_rn(__expf(v00 * 0.03125f), __expf(v01 * 0.03125f));
                __half2 h1 = __floats2half2_rn(__expf(v10 * 0.03125f), __expf(v11 * 0.03125f));
                *(__half2*)(C + (size_t)(m0 + r0) * ldC + n0 + c0) = h0;
                *(__half2*)(C + (size_t)(m0 + r1) * ldC + n0 + c0) = h1;
                bufT[(c0    ) * 132 + r0] = __low2half(h0);
                bufT[(c0 + 1) * 132 + r0] = __high2half(h0);
                bufT[(c0    ) * 132 + r1] = __low2half(h1);
                bufT[(c0 + 1) * 132 + r1] = __high2half(h1);
            } else {
                float2 f0 = make_float2(v00 * sc0, v01 * sc0);
                float2 f1 = make_float2(v10 * sc1, v11 * sc1);
                *(float2*)(Cf + (size_t)(m0 + r0) * ldC + n0 + c0) = f0;
                *(float2*)(Cf + (size_t)(m0 + r1) * ldC + n0 + c0) = f1;
            }
        }
    }

    if (MODE == 1) {
        __syncthreads();
        for (int r = wid * 16; r < wid * 16 + 16; r++) {
            uint32_t* dst32 = (uint32_t*)(C2 + (size_t)(n0 + r) * ldC2 + m0);
            const uint32_t* src32 = (const uint32_t*)(bufT + r * 132);
            dst32[lid]      = src32[lid];
            dst32[lid + 32] = src32[lid + 32];
        }
    }
}

// ============================================================================
// Helper kernels
// ============================================================================
// Fused: fp32 -> fp16 plane AND fp16 transposed plane (reads input once).
// in: [rows][cols] fp32; out: [rows][cols] fp16; outT: [cols][rows] fp16.
__global__ void convtrans_k(const float* __restrict__ in, __half* __restrict__ out,
                            __half* __restrict__ outT, int rows, int cols) {
    __shared__ float t[32][33];
    const int x0 = blockIdx.x * 32, y0 = blockIdx.y * 32;
    for (int j = threadIdx.y; j < 32; j += 8) {
        float v = in[(size_t)(y0 + j) * cols + x0 + threadIdx.x];
        t[j][threadIdx.x] = v;
        out[(size_t)(y0 + j) * cols + x0 + threadIdx.x] = __float2half_rn(v);
    }
    __syncthreads();
    for (int j = threadIdx.y; j < 32; j += 8)
        outT[(size_t)(x0 + j) * rows + y0 + threadIdx.x] = __float2half_rn(t[threadIdx.x][j]);
}

// Merged fp32->fp16 for both weight matrices (blockIdx.y selects).
__global__ void tohalf2_k(const float4* __restrict__ in0, __half2* __restrict__ out0,
                          const float4* __restrict__ in1, __half2* __restrict__ out1, int n4) {
    int i = blockIdx.x * blockDim.x + threadIdx.x;
    const float4* in = blockIdx.y ? in1 : in0;
    __half2* out     = blockIdx.y ? out1 : out0;
    if (i < n4) {
        float4 a = in[i];
        out[2 * i]     = __floats2half2_rn(a.x, a.y);
        out[2 * i + 1] = __floats2half2_rn(a.z, a.w);
    }
}

// Merged rowsum over P (y=0 -> rs) and PT (y=1 -> cs).
__global__ void rowsum_h2_k(const __half2* __restrict__ P0, float* __restrict__ out0,
                            const __half2* __restrict__ P1, float* __restrict__ out1,
                            int ncols) {
    __shared__ float red[256];
    const __half2* P2 = blockIdx.y ? P1 : P0;
    float* out        = blockIdx.y ? out1 : out0;
    const __half2* row = P2 + (size_t)blockIdx.x * (ncols / 2);
    float s = 0.0f;
    for (int j = threadIdx.x; j < ncols / 2; j += 256) {
        float2 v = __half22float2(row[j]);
        s += v.x + v.y;
    }
    red[threadIdx.x] = s;
    __syncthreads();
    for (int o = 128; o > 0; o >>= 1) {
        if (threadIdx.x < o) red[threadIdx.x] += red[threadIdx.x + o];
        __syncthreads();
    }
    if (threadIdx.x == 0) out[blockIdx.x] = red[0];
}

// ============================================================================
// Host launch
// ============================================================================
extern "C" void kernel_launch(void* const* d_in, const int* in_sizes, int n_in,
                              void* d_out, int out_size) {
    const float* text    = (const float*)d_in[0];
    const float* image   = (const float*)d_in[1];
    const float* w_text  = (const float*)d_in[2];
    const float* b_text  = (const float*)d_in[3];
    const float* w_image = (const float*)d_in[4];
    const float* b_image = (const float*)d_in[5];
    const float* s_TI    = (const float*)d_in[6];
    const float* s_IT    = (const float*)d_in[7];
    float* out = (float*)d_out;

    __half *tx, *im, *wt, *wi, *imT, *txT, *th, *ih, *P, *PT;
    float *rs, *cs;
    cudaGetSymbolAddress((void**)&tx,  g_tx);
    cudaGetSymbolAddress((void**)&im,  g_im);
    cudaGetSymbolAddress((void**)&wt,  g_wt);
    cudaGetSymbolAddress((void**)&wi,  g_wi);
    cudaGetSymbolAddress((void**)&imT, g_imT);
    cudaGetSymbolAddress((void**)&txT, g_txT);
    cudaGetSymbolAddress((void**)&th,  g_t);
    cudaGetSymbolAddress((void**)&ih,  g_i);
    cudaGetSymbolAddress((void**)&P,   g_P);
    cudaGetSymbolAddress((void**)&PT,  g_PT);
    cudaGetSymbolAddress((void**)&rs,  g_rowsum);
    cudaGetSymbolAddress((void**)&cs,  g_colsum);

    cudaFuncSetAttribute((const void*)gemm_h<0>, cudaFuncAttributeMaxDynamicSharedMemorySize, SMEM_H);
    cudaFuncSetAttribute((const void*)gemm_h<1>, cudaFuncAttributeMaxDynamicSharedMemorySize, SMEM_H);
    cudaFuncSetAttribute((const void*)gemm_h<2>, cudaFuncAttributeMaxDynamicSharedMemorySize, SMEM_H);

    // 1) fused fp16 conversion + transpose for text / image (reads fp32 once each)
    {
        dim3 blk(32, 8);
        dim3 grd(DIM / 32, N_TOK / 32);
        convtrans_k<<<grd, blk>>>(text,  tx, txT, N_TOK, DIM);
        convtrans_k<<<grd, blk>>>(image, im, imT, N_TOK, DIM);
    }
    // 2) weights -> fp16 (merged)
    {
        int w4 = DIM * DIM / 4;
        dim3 grd((w4 + 255) / 256, 2);
        tohalf2_k<<<grd, 256>>>((const float4*)w_text,  (__half2*)wt,
                                (const float4*)w_image, (__half2*)wi, w4);
    }
    // 3) projections merged:  t = text@wt^T+b_t (z=0),  i = image@wi^T+b_i (z=1)
    {
        dim3 grd(DIM / BN, N_TOK / BM, 2);
        gemm_h<0><<<grd, 256, SMEM_H>>>(tx, wt, im, wi, DIM, DIM, DIM,
                                        th, ih, DIM, nullptr, 0,
                                        nullptr, nullptr,
                                        b_text, b_image, nullptr, nullptr, nullptr, nullptr);
    }
    // 4) logits + exp:  P = exp((t @ i^T)/32),  PT = P^T
    {
        dim3 grd(N_TOK / BN, N_TOK / BM, 1);
        gemm_h<1><<<grd, 256, SMEM_H>>>(th, ih, th, ih, DIM, DIM, DIM,
                                        P, P, N_TOK, PT, N_TOK,
                                        nullptr, nullptr,
                                        nullptr, nullptr, nullptr, nullptr, nullptr, nullptr);
    }
    // 5) softmax denominators (merged)
    {
        dim3 grd(N_TOK, 2);
        rowsum_h2_k<<<grd, 256>>>((const __half2*)P, rs, (const __half2*)PT, cs, N_TOK);
    }
    // 6) outputs merged: out1 = (P@image)*s_TI/rs (z=0), out2 = (PT@text)*s_IT/cs (z=1)
    {
        dim3 grd(DIM / BN, N_TOK / BM, 2);
        gemm_h<2><<<grd, 256, SMEM_H>>>(P, imT, PT, txT, N_TOK, N_TOK, N_TOK,
                                        nullptr, nullptr, DIM, nullptr, 0,
                                        out, out + (size_t)N_TOK * DIM,
                                        nullptr, nullptr, rs, cs, s_TI, s_IT);
    }
}

// round 10
// speedup vs baseline: 2.2121x; 1.0329x over previous
#include <cuda_runtime.h>
#include <cuda_fp16.h>
#include <cstdint>
#include <cstddef>

// ============================================================================
// Problem constants
// ============================================================================
#define N_TOK 4096
#define DIM   1024

// ---- fp16 mma.sync m16n8k16 GEMM config ----
#define BM 128
#define BN 128
#define BKH 64                        // fp16 elems per K-stage (128 B/row)
#define LDH 72                        // padded smem row stride in halves (144 B)
#define TILE_H (128 * LDH)            // halves per tile (A or B)
#define BUF_H  (2 * TILE_H)           // A + B halves per stage
#define NSTAGE 3
#define SMEM_H (NSTAGE * BUF_H * 2)   // bytes = 110592

// ============================================================================
// Device scratch (fp16 planes; __device__ globals per allocation-free rule)
// ============================================================================
static __device__ __align__(256) __half g_tx  [N_TOK * DIM];
static __device__ __align__(256) __half g_im  [N_TOK * DIM];
static __device__ __align__(256) __half g_wt  [DIM * DIM];
static __device__ __align__(256) __half g_wi  [DIM * DIM];
static __device__ __align__(256) __half g_imT [DIM * N_TOK];
static __device__ __align__(256) __half g_txT [DIM * N_TOK];
static __device__ __align__(256) __half g_t   [N_TOK * DIM];
static __device__ __align__(256) __half g_i   [N_TOK * DIM];
static __device__ __align__(256) __half g_P   [(size_t)N_TOK * N_TOK];
static __device__ __align__(256) __half g_PT  [(size_t)N_TOK * N_TOK];
static __device__ __align__(256) float  g_rowsum[N_TOK];
static __device__ __align__(256) float  g_colsum[N_TOK];

// ============================================================================
// Helpers
// ============================================================================
__device__ __forceinline__ void cp_async16(void* dst_smem, const void* src) {
    uint32_t dst;
    asm("{ .reg .u64 t; cvta.to.shared.u64 t, %1; cvt.u32.u64 %0, t; }" : "=r"(dst) : "l"(dst_smem));
    asm volatile("cp.async.cg.shared.global [%0], [%1], 16;" :: "r"(dst), "l"(src) : "memory");
}
#define CP_COMMIT() asm volatile("cp.async.commit_group;" ::: "memory")
#define CP_WAIT(n)  asm volatile("cp.async.wait_group %0;" :: "n"(n) : "memory")

__device__ __forceinline__ uint32_t smem_addr32(const void* p) {
    uint32_t a;
    asm("{ .reg .u64 t; cvta.to.shared.u64 t, %1; cvt.u32.u64 %0, t; }" : "=r"(a) : "l"(p));
    return a;
}

__device__ __forceinline__ void ldsm_x4(uint32_t& r0, uint32_t& r1, uint32_t& r2, uint32_t& r3,
                                        uint32_t addr) {
    asm volatile("ldmatrix.sync.aligned.m8n8.x4.shared.b16 {%0,%1,%2,%3}, [%4];"
                 : "=r"(r0), "=r"(r1), "=r"(r2), "=r"(r3) : "r"(addr));
}

__device__ __forceinline__ void mma_f16(float& d0, float& d1, float& d2, float& d3,
                                        uint32_t a0, uint32_t a1, uint32_t a2, uint32_t a3,
                                        uint32_t b0, uint32_t b1) {
    asm volatile(
        "mma.sync.aligned.m16n8k16.row.col.f32.f16.f16.f32 "
        "{%0,%1,%2,%3}, {%4,%5,%6,%7}, {%8,%9}, {%0,%1,%2,%3};"
        : "+f"(d0), "+f"(d1), "+f"(d2), "+f"(d3)
        : "r"(a0), "r"(a1), "r"(a2), "r"(a3), "r"(b0), "r"(b1));
}

// ============================================================================
// fp16 GEMM:  D[m,n] = sum_k A[m,k] * B[n,k]   (NT, both K-major, fp32 accum)
// 3-stage cp.async pipeline, ONE __syncthreads per K-chunk.
// blockIdx.z in {0,1} selects pointer set (merged independent GEMMs).
// MODE 0: C[m,n] = h(D + bias[n])                           (projections, fp16 out)
// MODE 1: e = h(exp(D/32)); C[m,n]=e; C2[n,m]=e             (logits -> P, P^T, fp16)
// MODE 2: Cf[m,n] = D * scale[0] / denom[m]                 (attn @ V, fp32 out)
// ============================================================================
template <int MODE>
__global__ __launch_bounds__(256, 2)
void gemm_h(const __half* __restrict__ A0, const __half* __restrict__ B0,
            const __half* __restrict__ A1, const __half* __restrict__ B1,
            int K, int ldA, int ldB,
            __half* __restrict__ C0h, __half* __restrict__ C1h, int ldC,
            __half* __restrict__ C2, int ldC2,
            float* __restrict__ Cf0, float* __restrict__ Cf1,
            const float* __restrict__ bias0, const float* __restrict__ bias1,
            const float* __restrict__ denom0, const float* __restrict__ denom1,
            const float* __restrict__ scale0p, const float* __restrict__ scale1p)
{
    extern __shared__ __half smemh[];
    const int z   = blockIdx.z;
    const __half* __restrict__ A = z ? A1 : A0;
    const __half* __restrict__ B = z ? B1 : B0;
    __half* __restrict__ C       = z ? C1h : C0h;
    float*  __restrict__ Cf      = z ? Cf1 : Cf0;
    const float* __restrict__ bias  = z ? bias1  : bias0;
    const float* __restrict__ denom = z ? denom1 : denom0;
    const float* __restrict__ scale = z ? scale1p : scale0p;

    const int tid = threadIdx.x;
    const int wid = tid >> 5;
    const int lid = tid & 31;
    const int mw  = wid >> 2;       // 0..1 -> 64 rows
    const int nw  = wid & 3;        // 0..3 -> 32 cols
    const int m0  = blockIdx.y * BM;
    const int n0  = blockIdx.x * BN;

    const __half* __restrict__ Ab = A + (size_t)m0 * ldA;
    const __half* __restrict__ Bb = B + (size_t)n0 * ldB;

    const uint32_t sbase = smem_addr32(smemh);

    float acc[4][4][4];
    #pragma unroll
    for (int i = 0; i < 4; i++)
        #pragma unroll
        for (int j = 0; j < 4; j++)
            #pragma unroll
            for (int c = 0; c < 4; c++) acc[i][j][c] = 0.0f;

    const int NK = K / BKH;

    auto fill = [&](int kt) {
        const int bufI = kt % NSTAGE;
        const int kofs = kt * BKH;
        char* base = (char*)smemh + bufI * BUF_H * 2;
        #pragma unroll
        for (int i = 0; i < 8; i++) {
            const int idx = tid + i * 256;        // 0..2047 16B-chunks
            const int isB = idx >> 10;
            const int cc  = idx & 1023;
            const int row = cc >> 3;              // 0..127
            const int ch  = cc & 7;               // 16B chunk (8 halves)
            const __half* src = (isB ? (Bb + (size_t)row * ldB) : (Ab + (size_t)row * ldA))
                                + kofs + ch * 8;
            char* dst = base + (isB ? TILE_H * 2 : 0) + row * (LDH * 2) + ch * 16;
            cp_async16(dst, src);
        }
        CP_COMMIT();
    };

    // Prologue: fill NSTAGE-1 = 2 stages.
    fill(0);
    if (NK > 1) fill(1);

    // per-lane ldmatrix address offsets (bytes)
    const uint32_t a_lane = (uint32_t)(((lid & 15) * LDH + (lid >> 4) * 8) * 2);
    const uint32_t b_lane = (uint32_t)((((lid & 7) + ((lid >> 4) << 3)) * LDH
                                        + ((lid >> 3) & 1) * 8) * 2);

    for (int kt = 0; kt < NK; kt++) {
        const int b = kt % NSTAGE;
        // pending groups before wait: fill(kt) and (if issued) fill(kt+1)
        if (kt + 1 < NK) { CP_WAIT(1); } else { CP_WAIT(0); }
        __syncthreads();    // fill(kt) visible; all warps done reading stage (kt+2)%3

        // Write stage (kt+2)%3 — the stage read at iter kt-1; safe after the barrier.
        if (kt + 2 < NK) fill(kt + 2);

        const uint32_t Abase = sbase + (uint32_t)(b * BUF_H * 2) + (uint32_t)(mw * 64 * LDH * 2);
        const uint32_t Bbase = sbase + (uint32_t)(b * BUF_H * 2) + (uint32_t)(TILE_H * 2)
                             + (uint32_t)(nw * 32 * LDH * 2);

        #pragma unroll
        for (int ks = 0; ks < 4; ks++) {
            const uint32_t kb = (uint32_t)(ks * 16 * 2);
            uint32_t af[4][4];
            #pragma unroll
            for (int i = 0; i < 4; i++)
                ldsm_x4(af[i][0], af[i][1], af[i][2], af[i][3],
                        Abase + (uint32_t)(i * 16 * LDH * 2) + kb + a_lane);
            uint32_t bf[4][2];
            #pragma unroll
            for (int jj = 0; jj < 2; jj++)
                ldsm_x4(bf[jj * 2][0], bf[jj * 2][1], bf[jj * 2 + 1][0], bf[jj * 2 + 1][1],
                        Bbase + (uint32_t)(jj * 16 * LDH * 2) + kb + b_lane);
            #pragma unroll
            for (int i = 0; i < 4; i++)
                #pragma unroll
                for (int j = 0; j < 4; j++)
                    mma_f16(acc[i][j][0], acc[i][j][1], acc[i][j][2], acc[i][j][3],
                            af[i][0], af[i][1], af[i][2], af[i][3],
                            bf[j][0], bf[j][1]);
        }
        // no second barrier: stage b is not refilled until iter kt+1's barrier has
        // confirmed every warp left it (write stage trails read stage by 2).
    }

    // ---------------- Epilogue ----------------
    const int g = lid >> 2;
    const int q = lid & 3;
    const float sc_glob = (MODE == 2) ? scale[0] : 0.0f;
    __half* bufT = smemh;     // MODE 1 transpose staging: [128 n][132 m] halves
    if (MODE == 1) __syncthreads();   // all warps done with mainloop smem before reuse

    #pragma unroll
    for (int i = 0; i < 4; i++) {
        const int r0 = mw * 64 + i * 16 + g;
        const int r1 = r0 + 8;
        float sc0 = 1.0f, sc1 = 1.0f;
        if (MODE == 2) {
            sc0 = sc_glob / __ldg(&denom[m0 + r0]);
            sc1 = sc_glob / __ldg(&denom[m0 + r1]);
        }
        #pragma unroll
        for (int j = 0; j < 4; j++) {
            const int c0 = nw * 32 + j * 8 + 2 * q;
            float v00 = acc[i][j][0], v01 = acc[i][j][1];
            float v10 = acc[i][j][2], v11 = acc[i][j][3];
            if (MODE == 0) {
                const float b0 = __ldg(&bias[n0 + c0]);
                const float b1 = __ldg(&bias[n0 + c0 + 1]);
                __half2 h0 = __floats2half2_rn(v00 + b0, v01 + b1);
                __half2 h1 = __floats2half2_rn(v10 + b0, v11 + b1);
                *(__half2*)(C + (size_t)(m0 + r0) * ldC + n0 + c0) = h0;
                *(__half2*)(C + (size_t)(m0 + r1) * ldC + n0 + c0) = h1;
            } else if (MODE == 1) {
                __half2 h0 = __floats2half2_rn(__expf(v00 * 0.03125f), __expf(v01 * 0.03125f));
                __half2 h1 = __floats2half2_rn(__expf(v10 * 0.03125f), __expf(v11 * 0.03125f));
                *(__half2*)(C + (size_t)(m0 + r0) * ldC + n0 + c0) = h0;
                *(__half2*)(C + (size_t)(m0 + r1) * ldC + n0 + c0) = h1;
                bufT[(c0    ) * 132 + r0] = __low2half(h0);
                bufT[(c0 + 1) * 132 + r0] = __high2half(h0);
                bufT[(c0    ) * 132 + r1] = __low2half(h1);
                bufT[(c0 + 1) * 132 + r1] = __high2half(h1);
            } else {
                float2 f0 = make_float2(v00 * sc0, v01 * sc0);
                float2 f1 = make_float2(v10 * sc1, v11 * sc1);
                *(float2*)(Cf + (size_t)(m0 + r0) * ldC + n0 + c0) = f0;
                *(float2*)(Cf + (size_t)(m0 + r1) * ldC + n0 + c0) = f1;
            }
        }
    }

    if (MODE == 1) {
        __syncthreads();
        for (int r = wid * 16; r < wid * 16 + 16; r++) {
            uint32_t* dst32 = (uint32_t*)(C2 + (size_t)(n0 + r) * ldC2 + m0);
            const uint32_t* src32 = (const uint32_t*)(bufT + r * 132);
            dst32[lid]      = src32[lid];
            dst32[lid + 32] = src32[lid + 32];
        }
    }
}

// ============================================================================
// Helper kernels
// ============================================================================
// Fused: fp32 -> fp16 plane AND fp16 transposed plane; z selects text/image.
__global__ void convtrans2_k(const float* __restrict__ in0, __half* __restrict__ out0,
                             __half* __restrict__ out0T,
                             const float* __restrict__ in1, __half* __restrict__ out1,
                             __half* __restrict__ out1T, int rows, int cols) {
    __shared__ float t[32][33];
    const float* in = blockIdx.z ? in1 : in0;
    __half* out     = blockIdx.z ? out1 : out0;
    __half* outT    = blockIdx.z ? out1T : out0T;
    const int x0 = blockIdx.x * 32, y0 = blockIdx.y * 32;
    for (int j = threadIdx.y; j < 32; j += 8) {
        float v = in[(size_t)(y0 + j) * cols + x0 + threadIdx.x];
        t[j][threadIdx.x] = v;
        out[(size_t)(y0 + j) * cols + x0 + threadIdx.x] = __float2half_rn(v);
    }
    __syncthreads();
    for (int j = threadIdx.y; j < 32; j += 8)
        outT[(size_t)(x0 + j) * rows + y0 + threadIdx.x] = __float2half_rn(t[threadIdx.x][j]);
}

// Merged fp32->fp16 for both weight matrices (blockIdx.y selects).
__global__ void tohalf2_k(const float4* __restrict__ in0, __half2* __restrict__ out0,
                          const float4* __restrict__ in1, __half2* __restrict__ out1, int n4) {
    int i = blockIdx.x * blockDim.x + threadIdx.x;
    const float4* in = blockIdx.y ? in1 : in0;
    __half2* out     = blockIdx.y ? out1 : out0;
    if (i < n4) {
        float4 a = in[i];
        out[2 * i]     = __floats2half2_rn(a.x, a.y);
        out[2 * i + 1] = __floats2half2_rn(a.z, a.w);
    }
}

// Merged rowsum over P (y=0 -> rs) and PT (y=1 -> cs).
__global__ void rowsum_h2_k(const __half2* __restrict__ P0, float* __restrict__ out0,
                            const __half2* __restrict__ P1, float* __restrict__ out1,
                            int ncols) {
    __shared__ float red[256];
    const __half2* P2 = blockIdx.y ? P1 : P0;
    float* out        = blockIdx.y ? out1 : out0;
    const __half2* row = P2 + (size_t)blockIdx.x * (ncols / 2);
    float s = 0.0f;
    for (int j = threadIdx.x; j < ncols / 2; j += 256) {
        float2 v = __half22float2(row[j]);
        s += v.x + v.y;
    }
    red[threadIdx.x] = s;
    __syncthreads();
    for (int o = 128; o > 0; o >>= 1) {
        if (threadIdx.x < o) red[threadIdx.x] += red[threadIdx.x + o];
        __syncthreads();
    }
    if (threadIdx.x == 0) out[blockIdx.x] = red[0];
}

// ============================================================================
// Host launch
// ============================================================================
extern "C" void kernel_launch(void* const* d_in, const int* in_sizes, int n_in,
                              void* d_out, int out_size) {
    const float* text    = (const float*)d_in[0];
    const float* image   = (const float*)d_in[1];
    const float* w_text  = (const float*)d_in[2];
    const float* b_text  = (const float*)d_in[3];
    const float* w_image = (const float*)d_in[4];
    const float* b_image = (const float*)d_in[5];
    const float* s_TI    = (const float*)d_in[6];
    const float* s_IT    = (const float*)d_in[7];
    float* out = (float*)d_out;

    __half *tx, *im, *wt, *wi, *imT, *txT, *th, *ih, *P, *PT;
    float *rs, *cs;
    cudaGetSymbolAddress((void**)&tx,  g_tx);
    cudaGetSymbolAddress((void**)&im,  g_im);
    cudaGetSymbolAddress((void**)&wt,  g_wt);
    cudaGetSymbolAddress((void**)&wi,  g_wi);
    cudaGetSymbolAddress((void**)&imT, g_imT);
    cudaGetSymbolAddress((void**)&txT, g_txT);
    cudaGetSymbolAddress((void**)&th,  g_t);
    cudaGetSymbolAddress((void**)&ih,  g_i);
    cudaGetSymbolAddress((void**)&P,   g_P);
    cudaGetSymbolAddress((void**)&PT,  g_PT);
    cudaGetSymbolAddress((void**)&rs,  g_rowsum);
    cudaGetSymbolAddress((void**)&cs,  g_colsum);

    cudaFuncSetAttribute((const void*)gemm_h<0>, cudaFuncAttributeMaxDynamicSharedMemorySize, SMEM_H);
    cudaFuncSetAttribute((const void*)gemm_h<1>, cudaFuncAttributeMaxDynamicSharedMemorySize, SMEM_H);
    cudaFuncSetAttribute((const void*)gemm_h<2>, cudaFuncAttributeMaxDynamicSharedMemorySize, SMEM_H);

    // 1) fused fp16 conversion + transpose for text / image (single launch)
    {
        dim3 blk(32, 8);
        dim3 grd(DIM / 32, N_TOK / 32, 2);
        convtrans2_k<<<grd, blk>>>(text, tx, txT, image, im, imT, N_TOK, DIM);
    }
    // 2) weights -> fp16 (merged)
    {
        int w4 = DIM * DIM / 4;
        dim3 grd((w4 + 255) / 256, 2);
        tohalf2_k<<<grd, 256>>>((const float4*)w_text,  (__half2*)wt,
                                (const float4*)w_image, (__half2*)wi, w4);
    }
    // 3) projections merged:  t = text@wt^T+b_t (z=0),  i = image@wi^T+b_i (z=1)
    {
        dim3 grd(DIM / BN, N_TOK / BM, 2);
        gemm_h<0><<<grd, 256, SMEM_H>>>(tx, wt, im, wi, DIM, DIM, DIM,
                                        th, ih, DIM, nullptr, 0,
                                        nullptr, nullptr,
                                        b_text, b_image, nullptr, nullptr, nullptr, nullptr);
    }
    // 4) logits + exp:  P = exp((t @ i^T)/32),  PT = P^T
    {
        dim3 grd(N_TOK / BN, N_TOK / BM, 1);
        gemm_h<1><<<grd, 256, SMEM_H>>>(th, ih, th, ih, DIM, DIM, DIM,
                                        P, P, N_TOK, PT, N_TOK,
                                        nullptr, nullptr,
                                        nullptr, nullptr, nullptr, nullptr, nullptr, nullptr);
    }
    // 5) softmax denominators (merged)
    {
        dim3 grd(N_TOK, 2);
        rowsum_h2_k<<<grd, 256>>>((const __half2*)P, rs, (const __half2*)PT, cs, N_TOK);
    }
    // 6) outputs merged: out1 = (P@image)*s_TI/rs (z=0), out2 = (PT@text)*s_IT/cs (z=1)
    {
        dim3 grd(DIM / BN, N_TOK / BM, 2);
        gemm_h<2><<<grd, 256, SMEM_H>>>(P, imT, PT, txT, N_TOK, N_TOK, N_TOK,
                                        nullptr, nullptr, DIM, nullptr, 0,
                                        out, out + (size_t)N_TOK * DIM,
                                        nullptr, nullptr, rs, cs, s_TI, s_IT);
    }
}